// round 14
// baseline (speedup 1.0000x reference)
#include <cuda_runtime.h>
#include <cuda_bf16.h>
#include <math.h>

#define NCTA 32
#define NTHR 256
#define TSTEPS 512
#define NL 20
#define BUFSZ (2046 * 1024)

// ---------------- device globals (no allocation allowed) ----------------
__device__ __align__(16) float g_buf[BUFSZ];      // dilation buffers, slot = [b][k]
__device__ __align__(16) float g_resA[2][1024];   // res  [b][k], parity by layer
__device__ __align__(16) float g_hA[2][1024];     // h    [b][k], parity by layer
__device__ __align__(16) float g_skip[1024];      // relu(skip) [b][k]
__device__ __align__(16) float g_s[1024];         // relu(s)    [b][k]
__device__ __align__(16) float g_logits[2048];    // logits     [b][q]
__device__ __align__(16) float g_comp[19 * 256 * 128]; // composite Wr@res_w
__device__ unsigned g_cnt;
__device__ unsigned g_gen;

__constant__ int c_off[NL] = {0,1,3,7,15,31,63,127,255,511,
                              1023,1024,1026,1030,1038,1054,1086,1150,1278,1534};

__global__ void wn_init_kernel() {
    int i = blockIdx.x * blockDim.x + threadIdx.x;
    if (i == 0) { g_cnt = 0u; g_gen = 0u; }
    float4 z = make_float4(0.f, 0.f, 0.f, 0.f);
    float4* p = (float4*)g_buf;
    int n4 = BUFSZ / 4;
    for (int j = i; j < n4; j += gridDim.x * blockDim.x) p[j] = z;
}

// comp[l][zr][j] = sum_k causal_w[l+1][zr][k][1] * res_w[l][k][j]   (l = 0..18)
__global__ void __launch_bounds__(256) wn_comp_kernel(
    const float* __restrict__ causal_w, const float* __restrict__ res_w)
{
    int l = blockIdx.x >> 3, tile = blockIdx.x & 7;
    int zr0 = tile * 32;
    __shared__ float sCw[32 * 132];
    for (int i = threadIdx.x; i < 32 * 128; i += 256) {
        int r = i >> 7, k = i & 127;
        sCw[r * 132 + k] = causal_w[(size_t)(l + 1) * 65536 + (zr0 + r) * 256 + 2 * k + 1];
    }
    __syncthreads();
    int j = threadIdx.x & 127;
    int rg = threadIdx.x >> 7;            // 0..1 -> rows rg*16 .. rg*16+15
    float acc[16];
    #pragma unroll
    for (int i = 0; i < 16; i++) acc[i] = 0.f;
    const float* rw = res_w + (size_t)l * 16384;
    for (int k = 0; k < 128; k++) {
        float rv = __ldg(&rw[k * 128 + j]);    // coalesced across j
        #pragma unroll
        for (int i = 0; i < 16; i++)
            acc[i] = fmaf(sCw[(rg * 16 + i) * 132 + k], rv, acc[i]);
    }
    for (int i = 0; i < 16; i++)
        g_comp[(size_t)l * 32768 + (zr0 + rg * 16 + i) * 128 + j] = acc[i];
}

// ---- cp.async helpers ----
__device__ __forceinline__ void cpa16(void* s, const void* g) {
    unsigned sa = (unsigned)__cvta_generic_to_shared(s);
    asm volatile("cp.async.cg.shared.global [%0], [%1], 16;" :: "r"(sa), "l"(g) : "memory");
}
__device__ __forceinline__ void cpcommit() { asm volatile("cp.async.commit_group;" ::: "memory"); }
__device__ __forceinline__ void cpwait0()  { asm volatile("cp.async.wait_group 0;" ::: "memory"); }

// Monotonic global barrier, acquire/release.
__device__ __forceinline__ void gbar(unsigned target) {
    __syncthreads();
    if (threadIdx.x == 0) {
        unsigned old;
        asm volatile("atom.add.acq_rel.gpu.u32 %0, [%1], 1;"
                     : "=r"(old) : "l"(&g_cnt) : "memory");
        if (old == target * NCTA - 1u) {
            asm volatile("red.add.release.gpu.u32 [%0], 1;" :: "l"(&g_gen) : "memory");
        } else {
            unsigned g;
            do {
                asm volatile("ld.acquire.gpu.u32 %0, [%1];" : "=r"(g) : "l"(&g_gen) : "memory");
            } while (g < target);
        }
    }
    __syncthreads();
}

__device__ __forceinline__ float dot4(float4 a, float4 w) {
    return a.x*w.x + a.y*w.y + a.z*w.z + a.w*w.w;
}

__global__ void __launch_bounds__(NTHR, 1) wn_kernel(
    const float* __restrict__ enc,       const float* __restrict__ first_w,
    const float* __restrict__ first_b,   const float* __restrict__ causal_w,
    const float* __restrict__ causal_b,  const float* __restrict__ cond_w,
    const float* __restrict__ cond_b,    const float* __restrict__ res_w,
    const float* __restrict__ res_b,     const float* __restrict__ skip_w,
    const float* __restrict__ skip_b,    const float* __restrict__ skipc_w,
    const float* __restrict__ skipc_b,   const float* __restrict__ fc_w,
    const float* __restrict__ fc_b,      const float* __restrict__ condf_w,
    const float* __restrict__ condf_b,   const float* __restrict__ logits_w,
    const float* __restrict__ logits_b,
    float* __restrict__ out, int logits_base, int write_samples, int write_logits)
{
    __shared__ __align__(16) float sPrev[2][8 * 132];  // prev_lp at parity lp&1
    __shared__ __align__(16) float sRes [8 * 132];     // res_l full [b][k]
    __shared__ __align__(16) float sH   [8 * 132];     // h_l full   [b][k]
    __shared__ __align__(16) float sC   [8 * 68];      // c [b][m]
    __shared__ __align__(16) float sWz  [8 * 264];     // causal slice (w0,w1 interleaved)
    __shared__ __align__(16) float sComp[8 * 132];     // composite slice
    __shared__ __align__(16) float sWc  [8 * 68];      // cond slice
    __shared__ __align__(16) float sWrs [8 * 132];     // res rows 0-3, skip rows 4-7
    __shared__ __align__(16) float sSkc [4 * 132];     // persistent
    __shared__ __align__(16) float sFc  [4 * 132];     // persistent
    __shared__ __align__(16) float sCf  [4 * 68];      // persistent
    __shared__ __align__(16) float sLg  [8 * 132];     // persistent
    __shared__ __align__(16) float sFw[256];
    __shared__ __align__(16) float sFb[128];
    __shared__ __align__(16) float sBz[2][16];         // z biases, parity by ln
    __shared__ __align__(16) float sBrs[8];
    __shared__ float sSkcB[4], sFcB[4], sLgB[8];
    __shared__ float sPA[256], sPB[256], sPC[256];
    __shared__ float sSkip[32];
    __shared__ float sX[8], sPx[8];
    __shared__ int   sSmp[8];
    __shared__ float sAV[256];
    __shared__ int   sAI[256];

    const int tid = threadIdx.x;
    const int cta = blockIdx.x;
    const int q4 = tid >> 6;
    const int r8 = (tid >> 3) & 7;
    const int q8 = tid >> 5;
    const int r4 = (tid >> 3) & 3;
    const int b  = tid & 7;
    const int hb = cta * 4;
    const int lb = cta * 8;
    unsigned nb = 0;

    // ---------- persistent staging ----------
    for (int i = tid; i < 512; i += NTHR) {
        int r = i >> 7, k = i & 127;
        sSkc[r * 132 + k] = __ldg(&skipc_w[(hb + r) * 128 + k]);
        sFc [r * 132 + k] = __ldg(&fc_w   [(hb + r) * 128 + k]);
    }
    for (int i = tid; i < 256; i += NTHR) {
        int r = i >> 6, m = i & 63;
        sCf[r * 68 + m] = __ldg(&condf_w[(hb + r) * 64 + m]);
        sFw[i] = __ldg(&first_w[i]);
    }
    for (int i = tid; i < 1024; i += NTHR) {
        int r = i >> 7, k = i & 127;
        sLg[r * 132 + k] = __ldg(&logits_w[(lb + r) * 128 + k]);
        sPrev[0][(i >> 7) * 132 + (i & 127)] = 0.f;    // prev_0 at t=0 is zeros
    }
    for (int i = tid; i < 128; i += NTHR) sFb[i] = __ldg(&first_b[i]);
    if (tid < 4) {
        sSkcB[tid] = __ldg(&skipc_b[hb + tid]);
        sFcB[tid]  = __ldg(&fc_b[hb + tid]) + __ldg(&condf_b[hb + tid]);
    }
    if (tid < 8) sLgB[tid] = __ldg(&logits_b[lb + tid]);
    // layer-0 z weights + biases
    for (int i = tid; i < 2048; i += NTHR) {
        int rr = i >> 8, j = i & 255;
        int zr = (rr < 4) ? (hb + rr) : (128 + hb + rr - 4);
        sWz[rr * 264 + j] = __ldg(&causal_w[zr * 256 + j]);
    }
    for (int i = tid; i < 512; i += NTHR) {
        int rr = i >> 6, m = i & 63;
        int zr = (rr < 4) ? (hb + rr) : (128 + hb + rr - 4);
        sWc[rr * 68 + m] = __ldg(&cond_w[zr * 64 + m]);
    }
    if (tid < 4) {
        sBz[0][tid]      = __ldg(&causal_b[hb + tid]);
        sBz[0][4 + tid]  = __ldg(&causal_b[128 + hb + tid]);
        sBz[0][8 + tid]  = __ldg(&cond_b[hb + tid]);
        sBz[0][12 + tid] = __ldg(&cond_b[128 + hb + tid]);
    }
    if (tid < 8) { sPx[tid] = 0.f; sSmp[tid] = 128; }
    __syncthreads();

    for (int t = 0; t < TSTEPS; t++) {
        // ================= window A =================
        if ((t & 63) == 0) {
            int te = t >> 6;
            for (int i = tid; i < 512; i += NTHR) {
                int bb = i >> 6, m = i & 63;
                sC[bb * 68 + m] = __ldg(&enc[bb * 512 + m * 8 + te]);
            }
        }
        if (tid < 8) sX[tid] = (float)sSmp[tid] * (1.f / 255.f) - 0.5f;
        __syncthreads();
        // res_0 replicated [b][k]
        for (int i = tid; i < 1024; i += NTHR) {
            int bb = i >> 7, k = i & 127;
            sRes[bb * 132 + k] = sPx[bb] * sFw[2 * k] + sX[bb] * sFw[2 * k + 1] + sFb[k];
        }
        __syncthreads();
        if (tid < 8) sPx[tid] = sX[tid];
        // skip-init partial (sPA) + z_0 partial (sPB)
        {
            float acc = 0.f;
            #pragma unroll
            for (int g = 0; g < 4; g++) {
                int k0 = q8 * 16 + g * 4;
                acc += dot4(*(const float4*)&sRes[b * 132 + k0],
                            *(const float4*)&sSkc[r4 * 132 + k0]);
            }
            sPA[tid] = acc;
        }
        {
            float acc = 0.f;
            #pragma unroll
            for (int g = 0; g < 8; g++) {
                int k0 = q4 * 32 + g * 4;
                float4 pv  = *(const float4*)&sPrev[0][b * 132 + k0];
                float4 rv  = *(const float4*)&sRes[b * 132 + k0];
                float4 w01 = *(const float4*)&sWz[r8 * 264 + 2 * k0];
                float4 w23 = *(const float4*)&sWz[r8 * 264 + 2 * k0 + 4];
                acc = fmaf(pv.x, w01.x, acc); acc = fmaf(rv.x, w01.y, acc);
                acc = fmaf(pv.y, w01.z, acc); acc = fmaf(rv.y, w01.w, acc);
                acc = fmaf(pv.z, w23.x, acc); acc = fmaf(rv.z, w23.y, acc);
                acc = fmaf(pv.w, w23.z, acc); acc = fmaf(rv.w, w23.w, acc);
            }
            #pragma unroll
            for (int g = 0; g < 4; g++) {
                int m0 = q4 * 16 + g * 4;
                acc += dot4(*(const float4*)&sC [b  * 68 + m0],
                            *(const float4*)&sWc[r8 * 68 + m0]);
            }
            sPB[tid] = acc;
        }
        __syncthreads();
        if (tid < 32) {
            int r = tid >> 3, bb = tid & 7;
            float v = sSkcB[r];
            #pragma unroll
            for (int qq = 0; qq < 8; qq++) v += sPA[qq * 32 + tid];
            sSkip[tid] = v;
            float g = sBz[0][r]     + sBz[0][8 + r];
            float o = sBz[0][4 + r] + sBz[0][12 + r];
            #pragma unroll
            for (int qq = 0; qq < 4; qq++) {
                g += sPB[qq * 64 + r * 8 + bb];
                o += sPB[qq * 64 + (4 + r) * 8 + bb];
            }
            float sg = 1.f / (1.f + __expf(-g));
            float a  = fminf(fabsf(o), 15.f);
            float e  = __expf(2.f * a);
            float th = copysignf(__fdividef(e - 1.f, e + 1.f), o);
            __stcg(&g_hA[0][bb * 128 + hb + r], sg * th);
        }
        __syncthreads();
        // prefetch for B_0: z weights layer 1, comp_0, res/skip weights layer 0, prev_1
        {
            const float* cw  = causal_w + (size_t)65536;
            const float* cdw = cond_w   + (size_t)16384;
            #pragma unroll
            for (int rep = 0; rep < 2; rep++) {
                int i2 = tid + rep * 256;
                int rr = i2 >> 6, j = i2 & 63;
                int zr = (rr < 4) ? (hb + rr) : (128 + hb + rr - 4);
                cpa16(&sWz[rr * 264 + j * 4], cw + zr * 256 + j * 4);
            }
            if (tid < 128) {
                int rr = tid >> 4, j = tid & 15;
                int zr = (rr < 4) ? (hb + rr) : (128 + hb + rr - 4);
                cpa16(&sWc[rr * 68 + j * 4], cdw + zr * 64 + j * 4);
            }
            if (tid == 0) cpa16(&sBz[1][0],  causal_b + 256 + hb);
            if (tid == 1) cpa16(&sBz[1][4],  causal_b + 256 + 128 + hb);
            if (tid == 2) cpa16(&sBz[1][8],  cond_b   + 256 + hb);
            if (tid == 3) cpa16(&sBz[1][12], cond_b   + 256 + 128 + hb);
            {   // comp_0 slice
                int rr = tid >> 5, j = (tid & 31) * 4;
                int zr = (rr < 4) ? (hb + rr) : (128 + hb + rr - 4);
                cpa16(&sComp[rr * 132 + j], g_comp + zr * 128 + j);
            }
            if (tid < 128) {
                int rr = tid >> 5, j = tid & 31;
                cpa16(&sWrs[rr * 132 + j * 4], res_w + (hb + rr) * 128 + j * 4);
            } else {
                int i2 = tid - 128, rr = i2 >> 5, j = i2 & 31;
                cpa16(&sWrs[(4 + rr) * 132 + j * 4], skip_w + (hb + rr) * 128 + j * 4);
            }
            if (tid == 4) cpa16(&sBrs[0], res_b  + hb);
            if (tid == 5) cpa16(&sBrs[4], skip_b + hb);
            {   // prev_1: layer 1, d=2, slot = t&1  -> sPrev[1]
                int slot = t & 1;
                const float* src = g_buf + (size_t)(c_off[1] + slot) * 1024;
                int bp = tid >> 5, j = tid & 31;
                cpa16(&sPrev[1][bp * 132 + j * 4], src + bp * 128 + j * 4);
            }
        }
        cpcommit();
        gbar(++nb);   // h_0 barrier

        // ================= windows B_0 .. B_18 =================
        #pragma unroll 1
        for (int l = 0; l < NL - 1; l++) {
            const int par = l & 1, pn = par ^ 1;
            const int d = 1 << (l % 10);
            float* bufL = g_buf + (size_t)(c_off[l] + (t & (d - 1))) * 1024;

            {   // load h_l full (+ res_l full for l>=1)
                int bp = tid >> 5, j = tid & 31;
                cpa16(&sH[bp * 132 + j * 4], &g_hA[par][bp * 128 + j * 4]);
                if (l > 0) cpa16(&sRes[bp * 132 + j * 4], &g_resA[par][bp * 128 + j * 4]);
            }
            cpcommit();
            cpwait0();
            __syncthreads();

            // z_{l+1} partial: prev + res_l + comp_l@h_l + cond
            {
                float acc = 0.f;
                const float* pw = &sPrev[pn][0];
                #pragma unroll
                for (int g = 0; g < 8; g++) {
                    int k0 = q4 * 32 + g * 4;
                    float4 pv  = *(const float4*)&pw[b * 132 + k0];
                    float4 rv  = *(const float4*)&sRes[b * 132 + k0];
                    float4 w01 = *(const float4*)&sWz[r8 * 264 + 2 * k0];
                    float4 w23 = *(const float4*)&sWz[r8 * 264 + 2 * k0 + 4];
                    acc = fmaf(pv.x, w01.x, acc); acc = fmaf(rv.x, w01.y, acc);
                    acc = fmaf(pv.y, w01.z, acc); acc = fmaf(rv.y, w01.w, acc);
                    acc = fmaf(pv.z, w23.x, acc); acc = fmaf(rv.z, w23.y, acc);
                    acc = fmaf(pv.w, w23.z, acc); acc = fmaf(rv.w, w23.w, acc);
                }
                #pragma unroll
                for (int g = 0; g < 8; g++) {
                    int j0 = q4 * 32 + g * 4;
                    acc += dot4(*(const float4*)&sH[b * 132 + j0],
                                *(const float4*)&sComp[r8 * 132 + j0]);
                }
                #pragma unroll
                for (int g = 0; g < 4; g++) {
                    int m0 = q4 * 16 + g * 4;
                    acc += dot4(*(const float4*)&sC [b  * 68 + m0],
                                *(const float4*)&sWc[r8 * 68 + m0]);
                }
                sPA[tid] = acc;
            }
            __syncthreads();
            if (tid < 32) {   // z reduce + act + publish h_{l+1}
                int r = tid >> 3, bb = tid & 7;
                float g = sBz[pn][r]     + sBz[pn][8 + r];
                float o = sBz[pn][4 + r] + sBz[pn][12 + r];
                #pragma unroll
                for (int qq = 0; qq < 4; qq++) {
                    g += sPA[qq * 64 + r * 8 + bb];
                    o += sPA[qq * 64 + (4 + r) * 8 + bb];
                }
                float sg = 1.f / (1.f + __expf(-g));
                float a  = fminf(fabsf(o), 15.f);
                float e  = __expf(2.f * a);
                float th = copysignf(__fdividef(e - 1.f, e + 1.f), o);
                __stcg(&g_hA[pn][bb * 128 + hb + r], sg * th);
            }
            // res/skip partials (layer l weights)
            {
                float ar = 0.f, as = 0.f;
                #pragma unroll
                for (int g = 0; g < 4; g++) {
                    int k0 = q8 * 16 + g * 4;
                    float4 hv = *(const float4*)&sH[b * 132 + k0];
                    float4 rw = *(const float4*)&sWrs[r4 * 132 + k0];
                    float4 sw = *(const float4*)&sWrs[(4 + r4) * 132 + k0];
                    ar = fmaf(hv.x, rw.x, ar); ar = fmaf(hv.y, rw.y, ar);
                    ar = fmaf(hv.z, rw.z, ar); ar = fmaf(hv.w, rw.w, ar);
                    as = fmaf(hv.x, sw.x, as); as = fmaf(hv.y, sw.y, as);
                    as = fmaf(hv.z, sw.z, as); as = fmaf(hv.w, sw.w, as);
                }
                sPB[tid] = ar; sPC[tid] = as;
            }
            __syncthreads();
            if (tid < 32) {
                int r = tid >> 3, bb = tid & 7;
                float vr = sBrs[r], vs = sBrs[4 + r];
                #pragma unroll
                for (int qq = 0; qq < 8; qq++) {
                    vr += sPB[qq * 32 + tid];
                    vs += sPC[qq * 32 + tid];
                }
                sSkip[tid] += vs;
                vr += sRes[bb * 132 + hb + r];
                __stcg(&g_resA[pn][bb * 128 + hb + r], vr);          // res_{l+1} slice
                __stcg(&bufL[bb * 128 + hb + r], sRes[bb * 132 + hb + r]); // buf_l <- res_l
            }
            __syncthreads();
            // prefetch for next window
            if (l < NL - 2) {
                int ln2 = l + 2;
                const float* cw  = causal_w + (size_t)ln2 * 65536;
                const float* cdw = cond_w   + (size_t)ln2 * 16384;
                #pragma unroll
                for (int rep = 0; rep < 2; rep++) {
                    int i2 = tid + rep * 256;
                    int rr = i2 >> 6, j = i2 & 63;
                    int zr = (rr < 4) ? (hb + rr) : (128 + hb + rr - 4);
                    cpa16(&sWz[rr * 264 + j * 4], cw + zr * 256 + j * 4);
                }
                if (tid < 128) {
                    int rr = tid >> 4, j = tid & 15;
                    int zr = (rr < 4) ? (hb + rr) : (128 + hb + rr - 4);
                    cpa16(&sWc[rr * 68 + j * 4], cdw + zr * 64 + j * 4);
                }
                int pz = ln2 & 1;
                if (tid == 0) cpa16(&sBz[pz][0],  causal_b + ln2 * 256 + hb);
                if (tid == 1) cpa16(&sBz[pz][4],  causal_b + ln2 * 256 + 128 + hb);
                if (tid == 2) cpa16(&sBz[pz][8],  cond_b   + ln2 * 256 + hb);
                if (tid == 3) cpa16(&sBz[pz][12], cond_b   + ln2 * 256 + 128 + hb);
                {   // comp_{l+1}
                    int rr = tid >> 5, j = (tid & 31) * 4;
                    int zr = (rr < 4) ? (hb + rr) : (128 + hb + rr - 4);
                    cpa16(&sComp[rr * 132 + j],
                          g_comp + (size_t)(l + 1) * 32768 + zr * 128 + j);
                }
                {   // prev_{l+2} -> sPrev[par]
                    int dl = 1 << (ln2 % 10);
                    const float* src = g_buf + (size_t)(c_off[ln2] + (t & (dl - 1))) * 1024;
                    int bp = tid >> 5, j = tid & 31;
                    cpa16(&sPrev[par][bp * 132 + j * 4], src + bp * 128 + j * 4);
                }
            }
            {   // res_w/skip_w layer l+1
                int lw = l + 1;
                if (tid < 128) {
                    int rr = tid >> 5, j = tid & 31;
                    cpa16(&sWrs[rr * 132 + j * 4],
                          res_w + (size_t)lw * 16384 + (hb + rr) * 128 + j * 4);
                } else {
                    int i2 = tid - 128, rr = i2 >> 5, j = i2 & 31;
                    cpa16(&sWrs[(4 + rr) * 132 + j * 4],
                          skip_w + (size_t)lw * 16384 + (hb + rr) * 128 + j * 4);
                }
                if (tid == 4) cpa16(&sBrs[0], res_b  + lw * 128 + hb);
                if (tid == 5) cpa16(&sBrs[4], skip_b + lw * 128 + hb);
            }
            cpcommit();
            gbar(++nb);   // h_{l+1} barrier
        }

        // ================= window B_19 =================
        {
            const int par = 1;  // 19 & 1
            float* bufL = g_buf + (size_t)(c_off[19] + (t & 511)) * 1024;
            {
                int bp = tid >> 5, j = tid & 31;
                cpa16(&sH[bp * 132 + j * 4], &g_hA[par][bp * 128 + j * 4]);
                cpa16(&sRes[bp * 132 + j * 4], &g_resA[par][bp * 128 + j * 4]);
            }
            cpcommit(); cpwait0(); __syncthreads();
            {   // skip partial only
                float as = 0.f;
                #pragma unroll
                for (int g = 0; g < 4; g++) {
                    int k0 = q8 * 16 + g * 4;
                    float4 hv = *(const float4*)&sH[b * 132 + k0];
                    float4 sw = *(const float4*)&sWrs[(4 + r4) * 132 + k0];
                    as = fmaf(hv.x, sw.x, as); as = fmaf(hv.y, sw.y, as);
                    as = fmaf(hv.z, sw.z, as); as = fmaf(hv.w, sw.w, as);
                }
                sPC[tid] = as;
            }
            __syncthreads();
            if (tid < 32) {
                int r = tid >> 3, bb = tid & 7;
                float vs = sBrs[4 + r];
                #pragma unroll
                for (int qq = 0; qq < 8; qq++) vs += sPC[qq * 32 + tid];
                vs += sSkip[tid];
                __stcg(&bufL[bb * 128 + hb + r], sRes[bb * 132 + hb + r]);
                __stcg(&g_skip[bb * 128 + hb + r], fmaxf(vs, 0.f));
            }
            __syncthreads();
            // prefetch next step's window A: z weights layer 0 + prev_0
            {
                #pragma unroll
                for (int rep = 0; rep < 2; rep++) {
                    int i2 = tid + rep * 256;
                    int rr = i2 >> 6, j = i2 & 63;
                    int zr = (rr < 4) ? (hb + rr) : (128 + hb + rr - 4);
                    cpa16(&sWz[rr * 264 + j * 4], causal_w + zr * 256 + j * 4);
                }
                if (tid < 128) {
                    int rr = tid >> 4, j = tid & 15;
                    int zr = (rr < 4) ? (hb + rr) : (128 + hb + rr - 4);
                    cpa16(&sWc[rr * 68 + j * 4], cond_w + zr * 64 + j * 4);
                }
                if (tid == 0) cpa16(&sBz[0][0],  causal_b + hb);
                if (tid == 1) cpa16(&sBz[0][4],  causal_b + 128 + hb);
                if (tid == 2) cpa16(&sBz[0][8],  cond_b + hb);
                if (tid == 3) cpa16(&sBz[0][12], cond_b + 128 + hb);
                {   // prev_0 (d=1, slot 0) -> sPrev[0]
                    int bp = tid >> 5, j = tid & 31;
                    cpa16(&sPrev[0][bp * 132 + j * 4], g_buf + bp * 128 + j * 4);
                }
            }
            cpcommit();
            gbar(++nb);   // T0
        }

        // ================= tail =================
        {
            int bp = tid >> 5, j = tid & 31;
            cpa16(&sH[bp * 132 + j * 4], g_skip + bp * 128 + j * 4);
        }
        cpcommit(); cpwait0(); __syncthreads();
        {
            float acc = 0.f;
            #pragma unroll
            for (int g = 0; g < 4; g++) {
                int k0 = q8 * 16 + g * 4;
                acc += dot4(*(const float4*)&sH[b * 132 + k0],
                            *(const float4*)&sFc[r4 * 132 + k0]);
            }
            #pragma unroll
            for (int g = 0; g < 2; g++) {
                int m0 = q8 * 8 + g * 4;
                acc += dot4(*(const float4*)&sC [b  * 68 + m0],
                            *(const float4*)&sCf[r4 * 68 + m0]);
            }
            sPA[tid] = acc;
        }
        __syncthreads();
        if (tid < 32) {
            int r = tid >> 3, bb = tid & 7;
            float v = sFcB[r];
            #pragma unroll
            for (int qq = 0; qq < 8; qq++) v += sPA[qq * 32 + tid];
            __stcg(&g_s[bb * 128 + hb + r], fmaxf(v, 0.f));
        }
        gbar(++nb);   // T1
        {
            int bp = tid >> 5, j = tid & 31;
            cpa16(&sH[bp * 132 + j * 4], g_s + bp * 128 + j * 4);
        }
        cpcommit(); cpwait0(); __syncthreads();
        {
            float acc = 0.f;
            #pragma unroll
            for (int g = 0; g < 8; g++) {
                int k0 = q4 * 32 + g * 4;
                acc += dot4(*(const float4*)&sH[b * 132 + k0],
                            *(const float4*)&sLg[r8 * 132 + k0]);
            }
            sPA[tid] = acc;
        }
        __syncthreads();
        if (tid < 64) {
            int r = tid >> 3, bb = tid & 7;
            float v = sLgB[r] + sPA[tid] + sPA[64 + tid] + sPA[128 + tid] + sPA[192 + tid];
            int row = lb + r;
            __stcg(&g_logits[bb * 256 + row], v);
            if (write_logits) out[logits_base + t * 2048 + bb * 256 + row] = v;
        }
        gbar(++nb);   // T2
        // ---- replicated argmax (first-index tie-break) ----
        {
            int bb = tid & 7, chunk = tid >> 3;
            float bv = -1e30f; int bi = 0;
            #pragma unroll
            for (int j = 0; j < 8; j++) {
                int qrow = chunk * 8 + j;
                float v = __ldcg(&g_logits[bb * 256 + qrow]);
                if (v > bv) { bv = v; bi = qrow; }
            }
            sAV[tid] = bv; sAI[tid] = bi;
        }
        __syncthreads();
        if (tid < 8) {
            float bv = sAV[tid]; int bi = sAI[tid];
            for (int chunk = 1; chunk < 32; chunk++) {
                float v = sAV[chunk * 8 + tid];
                if (v > bv) { bv = v; bi = sAI[chunk * 8 + tid]; }
            }
            sSmp[tid] = bi;
            if (write_samples && cta == 0) out[t * 8 + tid] = (float)bi;
        }
        __syncthreads();
    }
}

extern "C" void kernel_launch(void* const* d_in, const int* in_sizes, int n_in,
                              void* d_out, int out_size) {
    wn_init_kernel<<<64, 256>>>();
    wn_comp_kernel<<<19 * 8, 256>>>((const float*)d_in[3], (const float*)d_in[7]);
    int wl = 0, ws = 0, lbase = 0;
    if (out_size >= 512 * 8 * 256) {
        wl = 1;
        lbase = out_size - 512 * 8 * 256;
        ws = (lbase >= 512 * 8) ? 1 : 0;
    } else if (out_size >= 512 * 8) {
        ws = 1;
    }
    wn_kernel<<<NCTA, NTHR>>>(
        (const float*)d_in[0],  (const float*)d_in[1],  (const float*)d_in[2],
        (const float*)d_in[3],  (const float*)d_in[4],  (const float*)d_in[5],
        (const float*)d_in[6],  (const float*)d_in[7],  (const float*)d_in[8],
        (const float*)d_in[9],  (const float*)d_in[10], (const float*)d_in[11],
        (const float*)d_in[12], (const float*)d_in[13], (const float*)d_in[14],
        (const float*)d_in[15], (const float*)d_in[16], (const float*)d_in[17],
        (const float*)d_in[18],
        (float*)d_out, lbase, ws, wl);
}

// round 17
// speedup vs baseline: 1.4707x; 1.4707x over previous
#include <cuda_runtime.h>
#include <cuda_bf16.h>
#include <math.h>

#define NCTA 32
#define NTHR 256
#define TSTEPS 512
#define NL 20
#define BUFSZ (2046 * 1024)

// ---------------- device globals (no allocation allowed) ----------------
__device__ __align__(16) float g_buf[BUFSZ];      // dilation buffers, slot = [b][k]
__device__ __align__(16) float g_resA[2][1024];   // res  [b][k], parity by layer
__device__ __align__(16) float g_hA[2][1024];     // h    [b][k], parity by layer
__device__ __align__(16) float g_skip[1024];      // relu(skip) [b][k]
__device__ __align__(16) float g_s[1024];         // relu(s)    [b][k]
__device__ __align__(16) float g_logits[2048];    // logits     [b][q]
__device__ __align__(16) float g_comp[19 * 256 * 128]; // composite Wr@res_w
__device__ unsigned g_cnt;
__device__ unsigned g_gen;

__constant__ int c_off[NL] = {0,1,3,7,15,31,63,127,255,511,
                              1023,1024,1026,1030,1038,1054,1086,1150,1278,1534};

__global__ void wn_init_kernel() {
    int i = blockIdx.x * blockDim.x + threadIdx.x;
    if (i == 0) { g_cnt = 0u; g_gen = 0u; }
    float4 z = make_float4(0.f, 0.f, 0.f, 0.f);
    float4* p = (float4*)g_buf;
    int n4 = BUFSZ / 4;
    for (int j = i; j < n4; j += gridDim.x * blockDim.x) p[j] = z;
}

// comp[l][zr][j] = sum_k causal_w[l+1][zr][k][1] * res_w[l][k][j]   (l = 0..18)
__global__ void __launch_bounds__(256) wn_comp_kernel(
    const float* __restrict__ causal_w, const float* __restrict__ res_w)
{
    int l = blockIdx.x >> 3, tile = blockIdx.x & 7;
    int zr0 = tile * 32;
    __shared__ float sCw[32 * 132];
    for (int i = threadIdx.x; i < 32 * 128; i += 256) {
        int r = i >> 7, k = i & 127;
        sCw[r * 132 + k] = causal_w[(size_t)(l + 1) * 65536 + (zr0 + r) * 256 + 2 * k + 1];
    }
    __syncthreads();
    int j = threadIdx.x & 127;
    int rg = threadIdx.x >> 7;            // 0..1 -> rows rg*16 .. rg*16+15
    float acc[16];
    #pragma unroll
    for (int i = 0; i < 16; i++) acc[i] = 0.f;
    const float* rw = res_w + (size_t)l * 16384;
    for (int k = 0; k < 128; k++) {
        float rv = __ldg(&rw[k * 128 + j]);    // coalesced across j
        #pragma unroll
        for (int i = 0; i < 16; i++)
            acc[i] = fmaf(sCw[(rg * 16 + i) * 132 + k], rv, acc[i]);
    }
    for (int i = 0; i < 16; i++)
        g_comp[(size_t)l * 32768 + (zr0 + rg * 16 + i) * 128 + j] = acc[i];
}

// ---- cp.async helpers ----
__device__ __forceinline__ void cpa16(void* s, const void* g) {
    unsigned sa = (unsigned)__cvta_generic_to_shared(s);
    asm volatile("cp.async.cg.shared.global [%0], [%1], 16;" :: "r"(sa), "l"(g) : "memory");
}
__device__ __forceinline__ void cpcommit() { asm volatile("cp.async.commit_group;" ::: "memory"); }
__device__ __forceinline__ void cpwait0()  { asm volatile("cp.async.wait_group 0;" ::: "memory"); }

// Monotonic global barrier, acquire/release.
__device__ __forceinline__ void gbar(unsigned target) {
    __syncthreads();
    if (threadIdx.x == 0) {
        unsigned old;
        asm volatile("atom.add.acq_rel.gpu.u32 %0, [%1], 1;"
                     : "=r"(old) : "l"(&g_cnt) : "memory");
        if (old == target * NCTA - 1u) {
            asm volatile("red.add.release.gpu.u32 [%0], 1;" :: "l"(&g_gen) : "memory");
        } else {
            unsigned g;
            do {
                asm volatile("ld.acquire.gpu.u32 %0, [%1];" : "=r"(g) : "l"(&g_gen) : "memory");
            } while (g < target);
        }
    }
    __syncthreads();
}

__device__ __forceinline__ float dot4(float4 a, float4 w) {
    return a.x*w.x + a.y*w.y + a.z*w.z + a.w*w.w;
}

__global__ void __launch_bounds__(NTHR, 1) wn_kernel(
    const float* __restrict__ enc,       const float* __restrict__ first_w,
    const float* __restrict__ first_b,   const float* __restrict__ causal_w,
    const float* __restrict__ causal_b,  const float* __restrict__ cond_w,
    const float* __restrict__ cond_b,    const float* __restrict__ res_w,
    const float* __restrict__ res_b,     const float* __restrict__ skip_w,
    const float* __restrict__ skip_b,    const float* __restrict__ skipc_w,
    const float* __restrict__ skipc_b,   const float* __restrict__ fc_w,
    const float* __restrict__ fc_b,      const float* __restrict__ condf_w,
    const float* __restrict__ condf_b,   const float* __restrict__ logits_w,
    const float* __restrict__ logits_b,
    float* __restrict__ out, int logits_base, int write_samples, int write_logits)
{
    __shared__ __align__(16) float sPrev[2][8 * 132];  // prev_lp at parity lp&1
    __shared__ __align__(16) float sRes [8 * 132];     // res_l full [b][k]
    __shared__ __align__(16) float sH   [8 * 132];     // h_l full   [b][k]
    __shared__ __align__(16) float sC   [8 * 68];      // c [b][m]
    __shared__ __align__(16) float sWz  [8 * 264];     // causal slice (w0,w1 interleaved)
    __shared__ __align__(16) float sComp[8 * 132];     // composite slice
    __shared__ __align__(16) float sWc  [8 * 68];      // cond slice
    __shared__ __align__(16) float sWrs [8 * 132];     // res rows 0-3, skip rows 4-7
    __shared__ __align__(16) float sSkc [4 * 132];     // persistent
    __shared__ __align__(16) float sFc  [4 * 132];     // persistent
    __shared__ __align__(16) float sCf  [4 * 68];      // persistent
    __shared__ __align__(16) float sLg  [8 * 132];     // persistent
    __shared__ __align__(16) float sFw[256];
    __shared__ __align__(16) float sFb[128];
    __shared__ __align__(16) float sBz[2][16];         // z biases, parity by ln
    __shared__ __align__(16) float sBrs[8];
    __shared__ float sSkcB[4], sFcB[4], sLgB[8];
    __shared__ float sPA[256], sPB[256], sPC[256];
    __shared__ float sSkip[32];
    __shared__ float sX[8], sPx[8];
    __shared__ int   sSmp[8];
    __shared__ float sAV[256];
    __shared__ int   sAI[256];

    const int tid = threadIdx.x;
    const int cta = blockIdx.x;
    const int q4 = tid >> 6;
    const int r8 = (tid >> 3) & 7;
    const int q8 = tid >> 5;
    const int r4 = (tid >> 3) & 3;
    const int b  = tid & 7;
    const int hb = cta * 4;
    const int lb = cta * 8;
    unsigned nb = 0;

    // ---------- persistent staging ----------
    for (int i = tid; i < 512; i += NTHR) {
        int r = i >> 7, k = i & 127;
        sSkc[r * 132 + k] = __ldg(&skipc_w[(hb + r) * 128 + k]);
        sFc [r * 132 + k] = __ldg(&fc_w   [(hb + r) * 128 + k]);
    }
    for (int i = tid; i < 256; i += NTHR) {
        int r = i >> 6, m = i & 63;
        sCf[r * 68 + m] = __ldg(&condf_w[(hb + r) * 64 + m]);
        sFw[i] = __ldg(&first_w[i]);
    }
    for (int i = tid; i < 1024; i += NTHR) {
        int r = i >> 7, k = i & 127;
        sLg[r * 132 + k] = __ldg(&logits_w[(lb + r) * 128 + k]);
        sPrev[0][(i >> 7) * 132 + (i & 127)] = 0.f;    // prev_0 at t=0 is zeros
    }
    for (int i = tid; i < 128; i += NTHR) sFb[i] = __ldg(&first_b[i]);
    if (tid < 4) {
        sSkcB[tid] = __ldg(&skipc_b[hb + tid]);
        sFcB[tid]  = __ldg(&fc_b[hb + tid]) + __ldg(&condf_b[hb + tid]);
    }
    if (tid < 8) sLgB[tid] = __ldg(&logits_b[lb + tid]);
    // layer-0 z weights + biases
    for (int i = tid; i < 2048; i += NTHR) {
        int rr = i >> 8, j = i & 255;
        int zr = (rr < 4) ? (hb + rr) : (128 + hb + rr - 4);
        sWz[rr * 264 + j] = __ldg(&causal_w[zr * 256 + j]);
    }
    for (int i = tid; i < 512; i += NTHR) {
        int rr = i >> 6, m = i & 63;
        int zr = (rr < 4) ? (hb + rr) : (128 + hb + rr - 4);
        sWc[rr * 68 + m] = __ldg(&cond_w[zr * 64 + m]);
    }
    if (tid < 4) {
        sBz[0][tid]      = __ldg(&causal_b[hb + tid]);
        sBz[0][4 + tid]  = __ldg(&causal_b[128 + hb + tid]);
        sBz[0][8 + tid]  = __ldg(&cond_b[hb + tid]);
        sBz[0][12 + tid] = __ldg(&cond_b[128 + hb + tid]);
    }
    if (tid < 8) { sPx[tid] = 0.f; sSmp[tid] = 128; }
    __syncthreads();

    for (int t = 0; t < TSTEPS; t++) {
        // ================= window A =================
        if ((t & 63) == 0) {
            int te = t >> 6;
            for (int i = tid; i < 512; i += NTHR) {
                int bb = i >> 6, m = i & 63;
                sC[bb * 68 + m] = __ldg(&enc[bb * 512 + m * 8 + te]);
            }
        }
        if (tid < 8) sX[tid] = (float)sSmp[tid] * (1.f / 255.f) - 0.5f;
        __syncthreads();
        // res_0 replicated [b][k]
        for (int i = tid; i < 1024; i += NTHR) {
            int bb = i >> 7, k = i & 127;
            sRes[bb * 132 + k] = sPx[bb] * sFw[2 * k] + sX[bb] * sFw[2 * k + 1] + sFb[k];
        }
        __syncthreads();
        if (tid < 8) sPx[tid] = sX[tid];
        // skip-init partial (sPA) + z_0 partial (sPB)
        {
            float acc = 0.f;
            #pragma unroll
            for (int g = 0; g < 4; g++) {
                int k0 = q8 * 16 + g * 4;
                acc += dot4(*(const float4*)&sRes[b * 132 + k0],
                            *(const float4*)&sSkc[r4 * 132 + k0]);
            }
            sPA[tid] = acc;
        }
        {
            float acc = 0.f;
            #pragma unroll
            for (int g = 0; g < 8; g++) {
                int k0 = q4 * 32 + g * 4;
                float4 pv  = *(const float4*)&sPrev[0][b * 132 + k0];
                float4 rv  = *(const float4*)&sRes[b * 132 + k0];
                float4 w01 = *(const float4*)&sWz[r8 * 264 + 2 * k0];
                float4 w23 = *(const float4*)&sWz[r8 * 264 + 2 * k0 + 4];
                acc = fmaf(pv.x, w01.x, acc); acc = fmaf(rv.x, w01.y, acc);
                acc = fmaf(pv.y, w01.z, acc); acc = fmaf(rv.y, w01.w, acc);
                acc = fmaf(pv.z, w23.x, acc); acc = fmaf(rv.z, w23.y, acc);
                acc = fmaf(pv.w, w23.z, acc); acc = fmaf(rv.w, w23.w, acc);
            }
            #pragma unroll
            for (int g = 0; g < 4; g++) {
                int m0 = q4 * 16 + g * 4;
                acc += dot4(*(const float4*)&sC [b  * 68 + m0],
                            *(const float4*)&sWc[r8 * 68 + m0]);
            }
            sPB[tid] = acc;
        }
        __syncthreads();
        if (tid < 32) {
            int r = tid >> 3, bb = tid & 7;
            float v = sSkcB[r];
            #pragma unroll
            for (int qq = 0; qq < 8; qq++) v += sPA[qq * 32 + tid];
            sSkip[tid] = v;
            float g = sBz[0][r]     + sBz[0][8 + r];
            float o = sBz[0][4 + r] + sBz[0][12 + r];
            #pragma unroll
            for (int qq = 0; qq < 4; qq++) {
                g += sPB[qq * 64 + r * 8 + bb];
                o += sPB[qq * 64 + (4 + r) * 8 + bb];
            }
            float sg = 1.f / (1.f + __expf(-g));
            float a  = fminf(fabsf(o), 15.f);
            float e  = __expf(2.f * a);
            float th = copysignf(__fdividef(e - 1.f, e + 1.f), o);
            __stcg(&g_hA[0][bb * 128 + hb + r], sg * th);
        }
        __syncthreads();
        // prefetch for B_0: z weights layer 1, comp_0, res/skip weights layer 0, prev_1
        {
            const float* cw  = causal_w + (size_t)65536;
            const float* cdw = cond_w   + (size_t)16384;
            #pragma unroll
            for (int rep = 0; rep < 2; rep++) {
                int i2 = tid + rep * 256;
                int rr = i2 >> 6, j = i2 & 63;
                int zr = (rr < 4) ? (hb + rr) : (128 + hb + rr - 4);
                cpa16(&sWz[rr * 264 + j * 4], cw + zr * 256 + j * 4);
            }
            if (tid < 128) {
                int rr = tid >> 4, j = tid & 15;
                int zr = (rr < 4) ? (hb + rr) : (128 + hb + rr - 4);
                cpa16(&sWc[rr * 68 + j * 4], cdw + zr * 64 + j * 4);
            }
            if (tid == 0) cpa16(&sBz[1][0],  causal_b + 256 + hb);
            if (tid == 1) cpa16(&sBz[1][4],  causal_b + 256 + 128 + hb);
            if (tid == 2) cpa16(&sBz[1][8],  cond_b   + 256 + hb);
            if (tid == 3) cpa16(&sBz[1][12], cond_b   + 256 + 128 + hb);
            {   // comp_0 slice
                int rr = tid >> 5, j = (tid & 31) * 4;
                int zr = (rr < 4) ? (hb + rr) : (128 + hb + rr - 4);
                cpa16(&sComp[rr * 132 + j], g_comp + zr * 128 + j);
            }
            if (tid < 128) {
                int rr = tid >> 5, j = tid & 31;
                cpa16(&sWrs[rr * 132 + j * 4], res_w + (hb + rr) * 128 + j * 4);
            } else {
                int i2 = tid - 128, rr = i2 >> 5, j = i2 & 31;
                cpa16(&sWrs[(4 + rr) * 132 + j * 4], skip_w + (hb + rr) * 128 + j * 4);
            }
            if (tid == 4) cpa16(&sBrs[0], res_b  + hb);
            if (tid == 5) cpa16(&sBrs[4], skip_b + hb);
            {   // prev_1: layer 1, d=2, slot = t&1  -> sPrev[1]
                int slot = t & 1;
                const float* src = g_buf + (size_t)(c_off[1] + slot) * 1024;
                int bp = tid >> 5, j = tid & 31;
                cpa16(&sPrev[1][bp * 132 + j * 4], src + bp * 128 + j * 4);
            }
        }
        cpcommit();
        gbar(++nb);   // h_0 barrier

        // ================= windows B_0 .. B_18 =================
        #pragma unroll 1
        for (int l = 0; l < NL - 1; l++) {
            const int par = l & 1, pn = par ^ 1;
            const int d = 1 << (l % 10);
            float* bufL = g_buf + (size_t)(c_off[l] + (t & (d - 1))) * 1024;

            {   // load h_l full (+ res_l full for l>=1)
                int bp = tid >> 5, j = tid & 31;
                cpa16(&sH[bp * 132 + j * 4], &g_hA[par][bp * 128 + j * 4]);
                if (l > 0) cpa16(&sRes[bp * 132 + j * 4], &g_resA[par][bp * 128 + j * 4]);
            }
            cpcommit();
            cpwait0();
            __syncthreads();

            // z_{l+1} partial: prev + res_l + comp_l@h_l + cond
            {
                float acc = 0.f;
                const float* pw = &sPrev[pn][0];
                #pragma unroll
                for (int g = 0; g < 8; g++) {
                    int k0 = q4 * 32 + g * 4;
                    float4 pv  = *(const float4*)&pw[b * 132 + k0];
                    float4 rv  = *(const float4*)&sRes[b * 132 + k0];
                    float4 w01 = *(const float4*)&sWz[r8 * 264 + 2 * k0];
                    float4 w23 = *(const float4*)&sWz[r8 * 264 + 2 * k0 + 4];
                    acc = fmaf(pv.x, w01.x, acc); acc = fmaf(rv.x, w01.y, acc);
                    acc = fmaf(pv.y, w01.z, acc); acc = fmaf(rv.y, w01.w, acc);
                    acc = fmaf(pv.z, w23.x, acc); acc = fmaf(rv.z, w23.y, acc);
                    acc = fmaf(pv.w, w23.z, acc); acc = fmaf(rv.w, w23.w, acc);
                }
                #pragma unroll
                for (int g = 0; g < 8; g++) {
                    int j0 = q4 * 32 + g * 4;
                    acc += dot4(*(const float4*)&sH[b * 132 + j0],
                                *(const float4*)&sComp[r8 * 132 + j0]);
                }
                #pragma unroll
                for (int g = 0; g < 4; g++) {
                    int m0 = q4 * 16 + g * 4;
                    acc += dot4(*(const float4*)&sC [b  * 68 + m0],
                                *(const float4*)&sWc[r8 * 68 + m0]);
                }
                sPA[tid] = acc;
            }
            __syncthreads();
            if (tid < 32) {   // z reduce + act + publish h_{l+1}
                int r = tid >> 3, bb = tid & 7;
                float g = sBz[pn][r]     + sBz[pn][8 + r];
                float o = sBz[pn][4 + r] + sBz[pn][12 + r];
                #pragma unroll
                for (int qq = 0; qq < 4; qq++) {
                    g += sPA[qq * 64 + r * 8 + bb];
                    o += sPA[qq * 64 + (4 + r) * 8 + bb];
                }
                float sg = 1.f / (1.f + __expf(-g));
                float a  = fminf(fabsf(o), 15.f);
                float e  = __expf(2.f * a);
                float th = copysignf(__fdividef(e - 1.f, e + 1.f), o);
                __stcg(&g_hA[pn][bb * 128 + hb + r], sg * th);
            }
            // res/skip partials (layer l weights)
            {
                float ar = 0.f, as = 0.f;
                #pragma unroll
                for (int g = 0; g < 4; g++) {
                    int k0 = q8 * 16 + g * 4;
                    float4 hv = *(const float4*)&sH[b * 132 + k0];
                    float4 rw = *(const float4*)&sWrs[r4 * 132 + k0];
                    float4 sw = *(const float4*)&sWrs[(4 + r4) * 132 + k0];
                    ar = fmaf(hv.x, rw.x, ar); ar = fmaf(hv.y, rw.y, ar);
                    ar = fmaf(hv.z, rw.z, ar); ar = fmaf(hv.w, rw.w, ar);
                    as = fmaf(hv.x, sw.x, as); as = fmaf(hv.y, sw.y, as);
                    as = fmaf(hv.z, sw.z, as); as = fmaf(hv.w, sw.w, as);
                }
                sPB[tid] = ar; sPC[tid] = as;
            }
            __syncthreads();
            if (tid < 32) {
                int r = tid >> 3, bb = tid & 7;
                float vr = sBrs[r], vs = sBrs[4 + r];
                #pragma unroll
                for (int qq = 0; qq < 8; qq++) {
                    vr += sPB[qq * 32 + tid];
                    vs += sPC[qq * 32 + tid];
                }
                sSkip[tid] += vs;
                vr += sRes[bb * 132 + hb + r];
                __stcg(&g_resA[pn][bb * 128 + hb + r], vr);          // res_{l+1} slice
                __stcg(&bufL[bb * 128 + hb + r], sRes[bb * 132 + hb + r]); // buf_l <- res_l
            }
            __syncthreads();
            // prefetch for next window
            if (l < NL - 2) {
                int ln2 = l + 2;
                const float* cw  = causal_w + (size_t)ln2 * 65536;
                const float* cdw = cond_w   + (size_t)ln2 * 16384;
                #pragma unroll
                for (int rep = 0; rep < 2; rep++) {
                    int i2 = tid + rep * 256;
                    int rr = i2 >> 6, j = i2 & 63;
                    int zr = (rr < 4) ? (hb + rr) : (128 + hb + rr - 4);
                    cpa16(&sWz[rr * 264 + j * 4], cw + zr * 256 + j * 4);
                }
                if (tid < 128) {
                    int rr = tid >> 4, j = tid & 15;
                    int zr = (rr < 4) ? (hb + rr) : (128 + hb + rr - 4);
                    cpa16(&sWc[rr * 68 + j * 4], cdw + zr * 64 + j * 4);
                }
                int pz = ln2 & 1;
                if (tid == 0) cpa16(&sBz[pz][0],  causal_b + ln2 * 256 + hb);
                if (tid == 1) cpa16(&sBz[pz][4],  causal_b + ln2 * 256 + 128 + hb);
                if (tid == 2) cpa16(&sBz[pz][8],  cond_b   + ln2 * 256 + hb);
                if (tid == 3) cpa16(&sBz[pz][12], cond_b   + ln2 * 256 + 128 + hb);
                {   // comp_{l+1}
                    int rr = tid >> 5, j = (tid & 31) * 4;
                    int zr = (rr < 4) ? (hb + rr) : (128 + hb + rr - 4);
                    cpa16(&sComp[rr * 132 + j],
                          g_comp + (size_t)(l + 1) * 32768 + zr * 128 + j);
                }
                {   // prev_{l+2} -> sPrev[par]
                    int dl = 1 << (ln2 % 10);
                    const float* src = g_buf + (size_t)(c_off[ln2] + (t & (dl - 1))) * 1024;
                    int bp = tid >> 5, j = tid & 31;
                    cpa16(&sPrev[par][bp * 132 + j * 4], src + bp * 128 + j * 4);
                }
            }
            {   // res_w/skip_w layer l+1
                int lw = l + 1;
                if (tid < 128) {
                    int rr = tid >> 5, j = tid & 31;
                    cpa16(&sWrs[rr * 132 + j * 4],
                          res_w + (size_t)lw * 16384 + (hb + rr) * 128 + j * 4);
                } else {
                    int i2 = tid - 128, rr = i2 >> 5, j = i2 & 31;
                    cpa16(&sWrs[(4 + rr) * 132 + j * 4],
                          skip_w + (size_t)lw * 16384 + (hb + rr) * 128 + j * 4);
                }
                if (tid == 4) cpa16(&sBrs[0], res_b  + lw * 128 + hb);
                if (tid == 5) cpa16(&sBrs[4], skip_b + lw * 128 + hb);
            }
            cpcommit();
            gbar(++nb);   // h_{l+1} barrier
        }

        // ================= window B_19 =================
        {
            const int par = 1;  // 19 & 1
            float* bufL = g_buf + (size_t)(c_off[19] + (t & 511)) * 1024;
            {
                int bp = tid >> 5, j = tid & 31;
                cpa16(&sH[bp * 132 + j * 4], &g_hA[par][bp * 128 + j * 4]);
                cpa16(&sRes[bp * 132 + j * 4], &g_resA[par][bp * 128 + j * 4]);
            }
            cpcommit(); cpwait0(); __syncthreads();
            {   // skip partial only
                float as = 0.f;
                #pragma unroll
                for (int g = 0; g < 4; g++) {
                    int k0 = q8 * 16 + g * 4;
                    float4 hv = *(const float4*)&sH[b * 132 + k0];
                    float4 sw = *(const float4*)&sWrs[(4 + r4) * 132 + k0];
                    as = fmaf(hv.x, sw.x, as); as = fmaf(hv.y, sw.y, as);
                    as = fmaf(hv.z, sw.z, as); as = fmaf(hv.w, sw.w, as);
                }
                sPC[tid] = as;
            }
            __syncthreads();
            if (tid < 32) {
                int r = tid >> 3, bb = tid & 7;
                float vs = sBrs[4 + r];
                #pragma unroll
                for (int qq = 0; qq < 8; qq++) vs += sPC[qq * 32 + tid];
                vs += sSkip[tid];
                __stcg(&bufL[bb * 128 + hb + r], sRes[bb * 132 + hb + r]);
                __stcg(&g_skip[bb * 128 + hb + r], fmaxf(vs, 0.f));
            }
            __syncthreads();
            // prefetch next step's window A: z weights layer 0 + prev_0
            {
                #pragma unroll
                for (int rep = 0; rep < 2; rep++) {
                    int i2 = tid + rep * 256;
                    int rr = i2 >> 6, j = i2 & 63;
                    int zr = (rr < 4) ? (hb + rr) : (128 + hb + rr - 4);
                    cpa16(&sWz[rr * 264 + j * 4], causal_w + zr * 256 + j * 4);
                }
                if (tid < 128) {
                    int rr = tid >> 4, j = tid & 15;
                    int zr = (rr < 4) ? (hb + rr) : (128 + hb + rr - 4);
                    cpa16(&sWc[rr * 68 + j * 4], cond_w + zr * 64 + j * 4);
                }
                if (tid == 0) cpa16(&sBz[0][0],  causal_b + hb);
                if (tid == 1) cpa16(&sBz[0][4],  causal_b + 128 + hb);
                if (tid == 2) cpa16(&sBz[0][8],  cond_b + hb);
                if (tid == 3) cpa16(&sBz[0][12], cond_b + 128 + hb);
                {   // prev_0 (d=1, slot 0) -> sPrev[0]
                    int bp = tid >> 5, j = tid & 31;
                    cpa16(&sPrev[0][bp * 132 + j * 4], g_buf + bp * 128 + j * 4);
                }
            }
            cpcommit();
            gbar(++nb);   // T0
        }

        // ================= tail =================
        {
            int bp = tid >> 5, j = tid & 31;
            cpa16(&sH[bp * 132 + j * 4], g_skip + bp * 128 + j * 4);
        }
        cpcommit(); cpwait0(); __syncthreads();
        {
            float acc = 0.f;
            #pragma unroll
            for (int g = 0; g < 4; g++) {
                int k0 = q8 * 16 + g * 4;
                acc += dot4(*(const float4*)&sH[b * 132 + k0],
                            *(const float4*)&sFc[r4 * 132 + k0]);
            }
            #pragma unroll
            for (int g = 0; g < 2; g++) {
                int m0 = q8 * 8 + g * 4;
                acc += dot4(*(const float4*)&sC [b  * 68 + m0],
                            *(const float4*)&sCf[r4 * 68 + m0]);
            }
            sPA[tid] = acc;
        }
        __syncthreads();
        if (tid < 32) {
            int r = tid >> 3, bb = tid & 7;
            float v = sFcB[r];
            #pragma unroll
            for (int qq = 0; qq < 8; qq++) v += sPA[qq * 32 + tid];
            __stcg(&g_s[bb * 128 + hb + r], fmaxf(v, 0.f));
        }
        gbar(++nb);   // T1
        {
            int bp = tid >> 5, j = tid & 31;
            cpa16(&sH[bp * 132 + j * 4], g_s + bp * 128 + j * 4);
        }
        cpcommit(); cpwait0(); __syncthreads();
        {
            float acc = 0.f;
            #pragma unroll
            for (int g = 0; g < 8; g++) {
                int k0 = q4 * 32 + g * 4;
                acc += dot4(*(const float4*)&sH[b * 132 + k0],
                            *(const float4*)&sLg[r8 * 132 + k0]);
            }
            sPA[tid] = acc;
        }
        __syncthreads();
        if (tid < 64) {
            int r = tid >> 3, bb = tid & 7;
            float v = sLgB[r] + sPA[tid] + sPA[64 + tid] + sPA[128 + tid] + sPA[192 + tid];
            int row = lb + r;
            __stcg(&g_logits[bb * 256 + row], v);
            if (write_logits) out[logits_base + t * 2048 + bb * 256 + row] = v;
        }
        gbar(++nb);   // T2
        // ---- replicated argmax (first-index tie-break) ----
        {
            int bb = tid & 7, chunk = tid >> 3;
            float bv = -1e30f; int bi = 0;
            #pragma unroll
            for (int j = 0; j < 8; j++) {
                int qrow = chunk * 8 + j;
                float v = __ldcg(&g_logits[bb * 256 + qrow]);
                if (v > bv) { bv = v; bi = qrow; }
            }
            sAV[tid] = bv; sAI[tid] = bi;
        }
        __syncthreads();
        if (tid < 8) {
            float bv = sAV[tid]; int bi = sAI[tid];
            for (int chunk = 1; chunk < 32; chunk++) {
                float v = sAV[chunk * 8 + tid];
                if (v > bv) { bv = v; bi = sAI[chunk * 8 + tid]; }
            }
            sSmp[tid] = bi;
            if (write_samples && cta == 0) out[t * 8 + tid] = (float)bi;
        }
        __syncthreads();
    }
}

extern "C" void kernel_launch(void* const* d_in, const int* in_sizes, int n_in,
                              void* d_out, int out_size) {
    wn_init_kernel<<<64, 256>>>();
    wn_comp_kernel<<<19 * 8, 256>>>((const float*)d_in[3], (const float*)d_in[7]);
    int wl = 0, ws = 0, lbase = 0;
    if (out_size >= 512 * 8 * 256) {
        wl = 1;
        lbase = out_size - 512 * 8 * 256;
        ws = (lbase >= 512 * 8) ? 1 : 0;
    } else if (out_size >= 512 * 8) {
        ws = 1;
    }
    wn_kernel<<<NCTA, NTHR>>>(
        (const float*)d_in[0],  (const float*)d_in[1],  (const float*)d_in[2],
        (const float*)d_in[3],  (const float*)d_in[4],  (const float*)d_in[5],
        (const float*)d_in[6],  (const float*)d_in[7],  (const float*)d_in[8],
        (const float*)d_in[9],  (const float*)d_in[10], (const float*)d_in[11],
        (const float*)d_in[12], (const float*)d_in[13], (const float*)d_in[14],
        (const float*)d_in[15], (const float*)d_in[16], (const float*)d_in[17],
        (const float*)d_in[18],
        (float*)d_out, lbase, ws, wl);
}